// round 6
// baseline (speedup 1.0000x reference)
#include <cuda_runtime.h>
#include <cstdint>

// ---------------- problem constants ----------------
static constexpr int BATCH    = 256;
static constexpr int NOUT     = 64;
static constexpr int KDIM     = 262144;          // 4*256*256
static constexpr int KTILE    = 32;              // fp32 per k-tile = 128 B
static constexpr int KT_TOTAL = KDIM / KTILE;    // 8192
static constexpr int NSPLIT   = 148;             // pure split-K, one CTA per SM

// padded smem rows: 32 data + 4 pad floats -> conflict-free fragment LDS
static constexpr int ROW_PAD       = 36;
static constexpr int A_ROWS        = 256;
static constexpr int B_ROWS        = 64;
static constexpr int A_STAGE_BYTES = A_ROWS * ROW_PAD * 4;   // 36864
static constexpr int B_BYTES       = B_ROWS * ROW_PAD * 4;   // 9216
static constexpr int NSTAGE        = 4;                      // A stages
static constexpr int SMEM_BYTES    = NSTAGE * A_STAGE_BYTES + B_BYTES;  // 156672

// ---------------- device scratch (no allocs allowed) ----------------
__device__ float g_Part[(size_t)NSPLIT * BATCH * NOUT];      // 9.7 MB split-K partials

// ---------------- helpers ----------------
__device__ __forceinline__ uint32_t smem_u32(const void* p) {
    uint32_t a;
    asm("{ .reg .u64 t; cvta.to.shared.u64 t, %1; cvt.u32.u64 %0, t; }" : "=r"(a) : "l"(p));
    return a;
}
__device__ __forceinline__ float to_tf32_f(float f) {
    float r; asm("cvt.rna.tf32.f32 %0, %1;" : "=f"(r) : "f"(f)); return r;
}
__device__ __forceinline__ uint32_t f2tf(float f) {
    uint32_t r; asm("cvt.rna.tf32.f32 %0, %1;" : "=r"(r) : "f"(f)); return r;
}
__device__ __forceinline__ void cp_async16(uint32_t s, const void* g) {
    asm volatile("cp.async.cg.shared.global [%0], [%1], 16;" :: "r"(s), "l"(g));
}
__device__ __forceinline__ void cp_commit() {
    asm volatile("cp.async.commit_group;" ::: "memory");
}
__device__ __forceinline__ void cp_wait3() {
    asm volatile("cp.async.wait_group 3;" ::: "memory");
}
__device__ __forceinline__ void mma_tf32(float* c, const uint32_t* a, const uint32_t* b) {
    asm volatile(
        "mma.sync.aligned.m16n8k8.row.col.f32.tf32.tf32.f32 "
        "{%0,%1,%2,%3}, {%4,%5,%6,%7}, {%8,%9}, {%0,%1,%2,%3};"
        : "+f"(c[0]), "+f"(c[1]), "+f"(c[2]), "+f"(c[3])
        : "r"(a[0]), "r"(a[1]), "r"(a[2]), "r"(a[3]), "r"(b[0]), "r"(b[1]));
}

// ---------------- fused split-K tf32 GEMM with on-the-fly DWT fold ----------------
// out = DWT(x) @ W.T = x @ Wp.T with
// Wp[o; ch, y=2i+r, xcol=2j+q] = 0.5*(W_LL + s_r W_LH + s_q W_HL + s_r s_q W_HH),
// W_w at W[o, ch*65536 + w*16384 + i*128 + j].
// grid = 148 CTAs, each: full M=256, N=64, K-tiles [t_begin, t_end)
// 8 warps = 4(M) x 2(N); warp tile 64x32; mma m16n8k8 tf32
__global__ __launch_bounds__(256, 1)
void gemm_fused_kernel(const float* __restrict__ x, const float* __restrict__ W) {
    extern __shared__ float smem[];
    const int tid  = threadIdx.x;
    const int lane = tid & 31;
    const int wid  = tid >> 5;
    const int wm   = wid >> 1;                    // 0..3 -> M offset wm*64
    const int wn   = wid & 1;                     // 0..1 -> N offset wn*32
    const int split = blockIdx.x;

    const int t_begin = (int)(((long)split * KT_TOTAL) / NSPLIT);
    const int t_end   = (int)(((long)(split + 1) * KT_TOTAL) / NSPLIT);
    const int nt      = t_end - t_begin;

    // ---- A producer mapping (cp.async): 2048 16B-chunks/stage, 8 per thread ----
    const int prow = tid >> 3;                    // 0..31, rows prow + u*32
    const int pci  = tid & 7;
    const float* gA = x + (size_t)prow * KDIM + (size_t)t_begin * KTILE + pci * 4;
    const uint32_t smem_b = smem_u32(smem);
    const uint32_t sA = smem_b + prow * (ROW_PAD * 4) + pci * 16;

    auto issue_A = [&](int s) {
        const uint32_t off = (uint32_t)(s & (NSTAGE - 1)) * A_STAGE_BYTES;
        const float* ga = gA + (size_t)s * KTILE;
        #pragma unroll
        for (int u = 0; u < 8; ++u)
            cp_async16(sA + off + u * (32 * ROW_PAD * 4), ga + (size_t)u * 32 * KDIM);
    };

    // ---- B producer mapping (LDG + butterfly + STS): 64 rows x 4 quarters ----
    const int brow = tid >> 2;                    // Wp output row o (0..63)
    const int jq   = tid & 3;                     // j-quarter within the k-tile
    const float* Wrow = W + (size_t)brow * KDIM + jq * 4;
    float* Bs = smem + NSTAGE * (A_STAGE_BYTES / 4);
    float* bsts = Bs + brow * ROW_PAD + jq * 8;

    auto load_B = [&](int s, float4* br) {        // prefetch 4 planes into regs
        const int k0  = (t_begin + s) * KTILE;
        const int c   = k0 >> 16;
        const int rem = k0 & 65535;
        const int i   = rem >> 9;                 // y>>1
        const int j0  = (rem & 255) >> 1;
        const float* wb = Wrow + c * 65536 + i * 128 + j0;
        br[0] = *reinterpret_cast<const float4*>(wb);
        br[1] = *reinterpret_cast<const float4*>(wb + 16384);
        br[2] = *reinterpret_cast<const float4*>(wb + 32768);
        br[3] = *reinterpret_cast<const float4*>(wb + 49152);
    };

    auto sts_B = [&](int s, const float4* br) {   // butterfly + tf32 round + STS
        const int y = ((t_begin + s) * KTILE & 65535) >> 8;
        const float sr = (y & 1) ? -1.0f : 1.0f;
        float u_[4], v_[4];
        u_[0] = fmaf(sr, br[1].x, br[0].x);  v_[0] = fmaf(sr, br[3].x, br[2].x);
        u_[1] = fmaf(sr, br[1].y, br[0].y);  v_[1] = fmaf(sr, br[3].y, br[2].y);
        u_[2] = fmaf(sr, br[1].z, br[0].z);  v_[2] = fmaf(sr, br[3].z, br[2].z);
        u_[3] = fmaf(sr, br[1].w, br[0].w);  v_[3] = fmaf(sr, br[3].w, br[2].w);
        float4 o0, o1;
        o0.x = to_tf32_f(0.5f * (u_[0] + v_[0]));
        o0.y = to_tf32_f(0.5f * (u_[0] - v_[0]));
        o0.z = to_tf32_f(0.5f * (u_[1] + v_[1]));
        o0.w = to_tf32_f(0.5f * (u_[1] - v_[1]));
        o1.x = to_tf32_f(0.5f * (u_[2] + v_[2]));
        o1.y = to_tf32_f(0.5f * (u_[2] - v_[2]));
        o1.z = to_tf32_f(0.5f * (u_[3] + v_[3]));
        o1.w = to_tf32_f(0.5f * (u_[3] - v_[3]));
        *reinterpret_cast<float4*>(bsts)     = o0;
        *reinterpret_cast<float4*>(bsts + 4) = o1;
    };

    // ---- accumulators ----
    float acc[4][4][4];
    #pragma unroll
    for (int mt = 0; mt < 4; ++mt)
        #pragma unroll
        for (int nb = 0; nb < 4; ++nb)
            #pragma unroll
            for (int r = 0; r < 4; ++r) acc[mt][nb][r] = 0.0f;

    const int g  = lane >> 2;                     // 0..7
    const int tg = lane & 3;                      // 0..3

    // ---- prologue ----
    issue_A(0); cp_commit();
    issue_A(1); cp_commit();
    issue_A(2); cp_commit();
    float4 bb0[4], bb1[4];
    load_B(0, bb0);

    // ---- mainloop: one tile per step, B regs ping-pong ----
    auto step = [&](int t, const float4* bcur, float4* bnxt) {
        if (t + 1 < nt) load_B(t + 1, bnxt);      // LDGs fly over this tile's work
        if (t + 3 < nt) issue_A(t + 3);           // A buffer (t+3)&3 = (t-1)&3: MMA(t-1) done
        cp_commit();                              // keep group count aligned
        sts_B(t, bcur);                           // safe: trailing sync of t-1 passed
        cp_wait3();                               // A stage t arrived
        __syncthreads();                          // A + B visible to all warps

        const float* As = smem + (size_t)(t & (NSTAGE - 1)) * (A_STAGE_BYTES / 4);
        #pragma unroll
        for (int ks = 0; ks < 4; ++ks) {          // 4 x K=8 per 32-float k-tile
            const int kc = ks * 8 + tg;
            uint32_t a[4][4], b[4][2];
            #pragma unroll
            for (int mt = 0; mt < 4; ++mt) {
                const float* ap = As + (size_t)(wm * 64 + mt * 16 + g) * ROW_PAD + kc;
                a[mt][0] = f2tf(ap[0]);
                a[mt][1] = f2tf(ap[8 * ROW_PAD]);
                a[mt][2] = f2tf(ap[4]);
                a[mt][3] = f2tf(ap[8 * ROW_PAD + 4]);
            }
            #pragma unroll
            for (int nb = 0; nb < 4; ++nb) {
                const float* bp = Bs + (size_t)(wn * 32 + nb * 8 + g) * ROW_PAD + kc;
                b[nb][0] = __float_as_uint(bp[0]);     // already tf32-rounded
                b[nb][1] = __float_as_uint(bp[4]);
            }
            #pragma unroll
            for (int mt = 0; mt < 4; ++mt)
                #pragma unroll
                for (int nb = 0; nb < 4; ++nb)
                    mma_tf32(acc[mt][nb], a[mt], b[nb]);
        }
        __syncthreads();                          // guard B + A-buffer reuse
    };

    int t = 0;
    while (t < nt) {
        step(t, bb0, bb1); ++t;
        if (t >= nt) break;
        step(t, bb1, bb0); ++t;
    }

    // ---- epilogue: write 256x64 partial for this split ----
    float* pp = g_Part + (size_t)split * (BATCH * NOUT);
    const int r0 = wm * 64 + g;
    const int c0 = wn * 32 + tg * 2;
    #pragma unroll
    for (int mt = 0; mt < 4; ++mt) {
        #pragma unroll
        for (int nb = 0; nb < 4; ++nb) {
            const int rr = r0 + mt * 16;
            const int cc = c0 + nb * 8;
            float2 v01 = make_float2(acc[mt][nb][0], acc[mt][nb][1]);
            float2 v23 = make_float2(acc[mt][nb][2], acc[mt][nb][3]);
            *reinterpret_cast<float2*>(pp + (size_t)rr * NOUT + cc)       = v01;
            *reinterpret_cast<float2*>(pp + (size_t)(rr + 8) * NOUT + cc) = v23;
        }
    }
}

// ---------------- reduce partials + bias ----------------
__global__ __launch_bounds__(256)
void reduce_kernel(const float* __restrict__ bias, float* __restrict__ out) {
    int idx = blockIdx.x * 256 + threadIdx.x;     // 16384 outputs
    int n = idx & 63;
    float acc = __ldg(bias + n);
    const float* p = g_Part + idx;
    #pragma unroll 4
    for (int s = 0; s < NSPLIT; ++s)
        acc += __ldg(p + (size_t)s * (BATCH * NOUT));
    out[idx] = acc;
}

// ---------------- launch ----------------
extern "C" void kernel_launch(void* const* d_in, const int* in_sizes, int n_in,
                              void* d_out, int out_size) {
    const float* x = (const float*)d_in[0];
    const float* W = (const float*)d_in[1];
    const float* b = (const float*)d_in[2];
    float* out = (float*)d_out;
    (void)in_sizes; (void)n_in; (void)out_size;

    cudaFuncSetAttribute(gemm_fused_kernel,
                         cudaFuncAttributeMaxDynamicSharedMemorySize, SMEM_BYTES);

    gemm_fused_kernel<<<NSPLIT, 256, SMEM_BYTES>>>(x, W);
    reduce_kernel<<<64, 256>>>(b, out);
}